// round 15
// baseline (speedup 1.0000x reference)
#include <cuda_runtime.h>
#include <math.h>

#define ALPHA 10.0f
#define NPTS  4096
#define NB    4
#define NG    (2 * NB)            // dir * batch groups = 8

#define BLOCK 128                 // threads per block (kernel 1)
#define RPT   8                   // rows per thread
#define JC    64                  // candidate chunks
#define CHUNK (NPTS / JC)         // 64 candidates per chunk
#define ROWTILES (NPTS / (BLOCK * RPT))  // 4

#define LSE_BLOCK   256
#define SUBS        8                     // lse blocks per group
#define SUBN        (NPTS / SUBS)         // 512 keys per lse block
#define KPT         (SUBN / LSE_BLOCK)    // 2 keys per thread

// Row keys of t = 2*(a.b - w) - ||a||^2  (min dist = -t), monotone UNSIGNED
// encoded so that 0 == "-inf" sentinel. Zero BSS covers the first call; the
// lse kernel restores zeros after reading (self-restoring graph).
__device__ unsigned int g_rowmax[NG * NPTS];
__device__ float g_partsum[NG * SUBS];    // per-(group,sub) exp partial sums
__device__ float g_lse[NG];
__device__ unsigned int g_ctrs[NG];       // per-group sub completion counters
__device__ unsigned int g_fin;            // group completion counter

// Monotone float -> unsigned key; u=0 is below every real key.
__device__ __forceinline__ unsigned int ukey(float f)
{
    int i = __float_as_int(f);
    return (i >= 0) ? ((unsigned int)i | 0x80000000u) : ~(unsigned int)i;
}
__device__ __forceinline__ float unukey(unsigned int u)
{
    int i = (u & 0x80000000u) ? (int)(u ^ 0x80000000u) : (int)~u;
    return __int_as_float(i);
}

// ---------------------------------------------------------------------------
// Packed fp32x2 helpers (sm_100a native)
// ---------------------------------------------------------------------------
__device__ __forceinline__ unsigned long long ffma2(unsigned long long a,
                                                    unsigned long long b,
                                                    unsigned long long c)
{
    unsigned long long d;
    asm("fma.rn.f32x2 %0, %1, %2, %3;" : "=l"(d) : "l"(a), "l"(b), "l"(c));
    return d;
}

__device__ __forceinline__ unsigned long long pack2(float lo, float hi)
{
    unsigned long long r;
    asm("mov.b64 %0, {%1, %2};" : "=l"(r) : "f"(lo), "f"(hi));
    return r;
}

__device__ __forceinline__ void unpack2(unsigned long long v, float& lo, float& hi)
{
    asm("mov.b64 {%0, %1}, %2;" : "=f"(lo), "=f"(hi) : "l"(v));
}

// ---------------------------------------------------------------------------
// Kernel 1: per (group, row) fold max_j of t = 2*(a.b - w) - ||a||^2 across
// candidate chunks with atomicMax on unsigned order-keys. Hot loop per
// candidate: 2 LDS.128 + 12 FFMA2 + 8 FMNMX => 8 pairs / 22 instrs.
// ---------------------------------------------------------------------------
__global__ void __launch_bounds__(BLOCK)
hausdorff_part_kernel(const float* __restrict__ p1,
                      const float* __restrict__ p2)
{
    // Each candidate: {bx,bx} {by,by} {bz,bz} {-w,-w}  (w = 0.5*||b||^2)
    __shared__ ulonglong2 sB[CHUNK * 2];   // 2 KB

    const int g   = blockIdx.z;            // 0..7
    const int dir = g >> 2;
    const int b   = g & 3;
    const int jc  = blockIdx.y;
    const int tid = threadIdx.x;

    const float* __restrict__ A  = dir ? p2 : p1;
    const float* __restrict__ Bv = dir ? p1 : p2;
    const float* __restrict__ Bb = Bv + ((size_t)b * NPTS + jc * CHUNK) * 3;

    // Fill smem: CHUNK(=64) candidates, threads 0..63.
    if (tid < CHUNK) {
        const int j = tid;
        float x = Bb[3 * j + 0];
        float y = Bb[3 * j + 1];
        float z = Bb[3 * j + 2];
        float w = -0.5f * (x * x + y * y + z * z);
        sB[2 * j + 0] = make_ulonglong2(pack2(x, x), pack2(y, y));
        sB[2 * j + 1] = make_ulonglong2(pack2(z, z), pack2(w, w));
    }
    __syncthreads();

    // Load 8 rows (strided by BLOCK for coalescing) and pack pairs.
    const int rowbase = blockIdx.x * (BLOCK * RPT);
    float ax[RPT], ay[RPT], az[RPT];
#pragma unroll
    for (int k = 0; k < RPT; ++k) {
        const int i = rowbase + tid + k * BLOCK;
        const float* __restrict__ Ai = A + ((size_t)b * NPTS + i) * 3;
        ax[k] = Ai[0];
        ay[k] = Ai[1];
        az[k] = Ai[2];
    }
    unsigned long long pax[RPT / 2], pay[RPT / 2], paz[RPT / 2];
#pragma unroll
    for (int p = 0; p < RPT / 2; ++p) {
        pax[p] = pack2(ax[2 * p], ax[2 * p + 1]);
        pay[p] = pack2(ay[2 * p], ay[2 * p + 1]);
        paz[p] = pack2(az[2 * p], az[2 * p + 1]);
    }

    float m[RPT];
#pragma unroll
    for (int k = 0; k < RPT; ++k) m[k] = -3.402823466e38f;

#pragma unroll 4
    for (int j = 0; j < CHUNK; ++j) {
        const ulonglong2 q0 = sB[2 * j + 0];   // {bx,bx} {by,by}
        const ulonglong2 q1 = sB[2 * j + 1];   // {bz,bz} {-w,-w}
#pragma unroll
        for (int p = 0; p < RPT / 2; ++p) {
            unsigned long long s = ffma2(pax[p], q0.x, q1.y);
            s = ffma2(pay[p], q0.y, s);
            s = ffma2(paz[p], q1.x, s);
            float s0, s1;
            unpack2(s, s0, s1);
            m[2 * p + 0] = fmaxf(m[2 * p + 0], s0);
            m[2 * p + 1] = fmaxf(m[2 * p + 1], s1);
        }
    }

    // t = 2*m - sq;  min dist = -t.  Max is order-independent => determinist.
#pragma unroll
    for (int k = 0; k < RPT; ++k) {
        const int row = rowbase + tid + k * BLOCK;
        const float sq = fmaf(ax[k], ax[k], fmaf(ay[k], ay[k], az[k] * az[k]));
        const float t  = fmaf(2.0f, m[k], -sq);
        atomicMax(&g_rowmax[g * NPTS + row], ukey(t));
    }
}

// ---------------------------------------------------------------------------
// Kernel 2: parallel lse, NO max-pass. v = ALPHA * min_dist >= 0, and for
// this data v << 88 (exp overflow), so exp(v) directly is exact w.r.t. the
// reference logsumexp. grid = NG*SUBS = 64 blocks; each sums 512 exps; the
// last block per group combines its 8 partials IN FIXED ORDER (determinist),
// and the last group writes the final scalar. Self-restoring: key sentinels
// rewritten, counters reset.
// ---------------------------------------------------------------------------
__global__ void __launch_bounds__(LSE_BLOCK)
hausdorff_lse_kernel(float* __restrict__ out)
{
    __shared__ float sred[LSE_BLOCK / 32];
    __shared__ bool s_elect, s_fin;

    const int gb   = blockIdx.x;          // 0..63
    const int g    = gb >> 3;             // group
    const int sub  = gb & 7;              // sub-slice within group
    const int tid  = threadIdx.x;
    const int lane = tid & 31;
    const int wid  = tid >> 5;

    uint2* __restrict__ keys =
        (uint2*)(g_rowmax + g * NPTS + sub * SUBN);

    // 2 keys/thread, coalesced 8B; restore sentinel after read.
    uint2 kk = keys[tid];
    keys[tid] = make_uint2(0u, 0u);
    const float v0 = -ALPHA * unukey(kk.x);  // = ALPHA * min_dist >= 0
    const float v1 = -ALPHA * unukey(kk.y);
    float acc = __expf(v0) + __expf(v1);

    // warp sum + 8-partial block sum
#pragma unroll
    for (int o = 16; o > 0; o >>= 1)
        acc += __shfl_xor_sync(0xFFFFFFFFu, acc, o);
    if (lane == 0) sred[wid] = acc;
    __syncthreads();

    if (tid == 0) {
        float blocksum = 0.0f;
#pragma unroll
        for (int i = 0; i < LSE_BLOCK / 32; ++i) blocksum += sred[i];
        g_partsum[g * SUBS + sub] = blocksum;
        __threadfence();
        unsigned int prev = atomicAdd(&g_ctrs[g], 1u);
        s_elect = (prev == SUBS - 1);
    }
    __syncthreads();

    if (!s_elect) return;

    if (tid == 0) {
        // Fixed-order combine of the 8 sub partials: deterministic.
        float total = 0.0f;
#pragma unroll
        for (int i = 0; i < SUBS; ++i)
            total += __ldcg(&g_partsum[g * SUBS + i]);
        g_lse[g] = __logf(total) / ALPHA;
        g_ctrs[g] = 0u;                    // reset for next replay
        __threadfence();
        unsigned int prev = atomicAdd(&g_fin, 1u);
        s_fin = (prev == NG - 1);
    }
    __syncthreads();

    if (s_fin && tid == 0) {
        float a = 0.0f, c = 0.0f;
        for (int i = 0; i < NB; ++i) {
            a += __ldcg(&g_lse[i]);
            c += __ldcg(&g_lse[NB + i]);
        }
        out[0] = 0.5f * (a / NB + c / NB);
        atomicExch(&g_fin, 0u);            // reset for next replay
    }
}

// ---------------------------------------------------------------------------
extern "C" void kernel_launch(void* const* d_in, const int* in_sizes, int n_in,
                              void* d_out, int out_size)
{
    const float* p1 = (const float*)d_in[0];
    const float* p2 = (const float*)d_in[1];
    float* out = (float*)d_out;

    dim3 grid(ROWTILES, JC, NG);   // 4 x 64 x 8 = 2048 blocks
    hausdorff_part_kernel<<<grid, BLOCK>>>(p1, p2);
    hausdorff_lse_kernel<<<NG * SUBS, LSE_BLOCK>>>(out);
}

// round 16
// speedup vs baseline: 1.0089x; 1.0089x over previous
#include <cuda_runtime.h>
#include <math.h>

#define ALPHA 10.0f
#define NPTS  4096
#define NB    4
#define NG    (2 * NB)            // dir * batch groups = 8

#define BLOCK 128                 // threads per block
#define RPT   8                   // rows per thread
#define JC    64                  // candidate chunks
#define CHUNK (NPTS / JC)         // 64 candidates per chunk
#define ROWTILES (NPTS / (BLOCK * RPT))  // 4
#define BLOCKS_PER_G (ROWTILES * JC)     // 256

#define KPT (NPTS / BLOCK / 4)    // 8 x uint4 per thread in the tail

// Row keys of t = 2*(a.b - w) - ||a||^2  (min dist = -t), monotone UNSIGNED
// encoded so that 0 == "-inf" sentinel. Zero BSS covers the first call; the
// elected tail restores zeros after reading (self-restoring graph).
__device__ unsigned int g_rowmax[NG * NPTS];
__device__ float g_lse[NG];
__device__ unsigned int g_done[NG];   // per-group completion counters
__device__ unsigned int g_fin;        // group completion counter

// Monotone float -> unsigned key; u=0 is below every real key.
__device__ __forceinline__ unsigned int ukey(float f)
{
    int i = __float_as_int(f);
    return (i >= 0) ? ((unsigned int)i | 0x80000000u) : ~(unsigned int)i;
}
__device__ __forceinline__ float unukey(unsigned int u)
{
    int i = (u & 0x80000000u) ? (int)(u ^ 0x80000000u) : (int)~u;
    return __int_as_float(i);
}

// ---------------------------------------------------------------------------
// Packed fp32x2 helpers (sm_100a native)
// ---------------------------------------------------------------------------
__device__ __forceinline__ unsigned long long ffma2(unsigned long long a,
                                                    unsigned long long b,
                                                    unsigned long long c)
{
    unsigned long long d;
    asm("fma.rn.f32x2 %0, %1, %2, %3;" : "=l"(d) : "l"(a), "l"(b), "l"(c));
    return d;
}

__device__ __forceinline__ unsigned long long pack2(float lo, float hi)
{
    unsigned long long r;
    asm("mov.b64 %0, {%1, %2};" : "=l"(r) : "f"(lo), "f"(hi));
    return r;
}

__device__ __forceinline__ void unpack2(unsigned long long v, float& lo, float& hi)
{
    asm("mov.b64 {%0, %1}, %2;" : "=f"(lo), "=f"(hi) : "l"(v));
}

// ---------------------------------------------------------------------------
// Single fused kernel.
// Phase 1 (all 2048 blocks): per (group,row) fold max_j of
//   t = 2*(a.b - w) - ||a||^2  across candidate chunks via atomicMax.
// Hot loop per candidate: 2 LDS.128 + 12 FFMA2 + 8 FMNMX => 8 pairs/22 instr.
// Phase 2 (last block of each group): lean lse tail — no max-pass
// (v = ALPHA*min_dist in [0, ~tens], far under exp overflow), 16KB L2 read,
// MUFU __expf, shuffle reduction. Last group writes the scalar.
// Self-restoring: key sentinels + counters reset for graph replay.
// ---------------------------------------------------------------------------
__global__ void __launch_bounds__(BLOCK)
hausdorff_fused_kernel(const float* __restrict__ p1,
                       const float* __restrict__ p2,
                       float* __restrict__ out)
{
    __shared__ ulonglong2 sB[CHUNK * 2];   // 2 KB
    __shared__ float sred[BLOCK / 32];
    __shared__ bool s_lastg, s_fin;

    const int g   = blockIdx.z;            // 0..7
    const int dir = g >> 2;
    const int b   = g & 3;
    const int jc  = blockIdx.y;
    const int tid = threadIdx.x;

    const float* __restrict__ A  = dir ? p2 : p1;
    const float* __restrict__ Bv = dir ? p1 : p2;
    const float* __restrict__ Bb = Bv + ((size_t)b * NPTS + jc * CHUNK) * 3;

    // Fill smem: CHUNK(=64) candidates, threads 0..63.
    if (tid < CHUNK) {
        const int j = tid;
        float x = Bb[3 * j + 0];
        float y = Bb[3 * j + 1];
        float z = Bb[3 * j + 2];
        float w = -0.5f * (x * x + y * y + z * z);
        sB[2 * j + 0] = make_ulonglong2(pack2(x, x), pack2(y, y));
        sB[2 * j + 1] = make_ulonglong2(pack2(z, z), pack2(w, w));
    }
    __syncthreads();

    // Load 8 rows (strided by BLOCK for coalescing) and pack pairs.
    const int rowbase = blockIdx.x * (BLOCK * RPT);
    float ax[RPT], ay[RPT], az[RPT];
#pragma unroll
    for (int k = 0; k < RPT; ++k) {
        const int i = rowbase + tid + k * BLOCK;
        const float* __restrict__ Ai = A + ((size_t)b * NPTS + i) * 3;
        ax[k] = Ai[0];
        ay[k] = Ai[1];
        az[k] = Ai[2];
    }
    unsigned long long pax[RPT / 2], pay[RPT / 2], paz[RPT / 2];
#pragma unroll
    for (int p = 0; p < RPT / 2; ++p) {
        pax[p] = pack2(ax[2 * p], ax[2 * p + 1]);
        pay[p] = pack2(ay[2 * p], ay[2 * p + 1]);
        paz[p] = pack2(az[2 * p], az[2 * p + 1]);
    }

    float m[RPT];
#pragma unroll
    for (int k = 0; k < RPT; ++k) m[k] = -3.402823466e38f;

#pragma unroll 4
    for (int j = 0; j < CHUNK; ++j) {
        const ulonglong2 q0 = sB[2 * j + 0];   // {bx,bx} {by,by}
        const ulonglong2 q1 = sB[2 * j + 1];   // {bz,bz} {-w,-w}
#pragma unroll
        for (int p = 0; p < RPT / 2; ++p) {
            unsigned long long s = ffma2(pax[p], q0.x, q1.y);
            s = ffma2(pay[p], q0.y, s);
            s = ffma2(paz[p], q1.x, s);
            float s0, s1;
            unpack2(s, s0, s1);
            m[2 * p + 0] = fmaxf(m[2 * p + 0], s0);
            m[2 * p + 1] = fmaxf(m[2 * p + 1], s1);
        }
    }

    // t = 2*m - sq;  min dist = -t.  Max is order-independent => determinist.
#pragma unroll
    for (int k = 0; k < RPT; ++k) {
        const int row = rowbase + tid + k * BLOCK;
        const float sq = fmaf(ax[k], ax[k], fmaf(ay[k], ay[k], az[k] * az[k]));
        const float t  = fmaf(2.0f, m[k], -sq);
        atomicMax(&g_rowmax[g * NPTS + row], ukey(t));
    }

    // ---- Elect the last-finishing block of this group. ----
    if (tid == 0) {
        __threadfence();
        unsigned int prev = atomicAdd(&g_done[g], 1u);
        s_lastg = (prev == BLOCKS_PER_G - 1);
    }
    __syncthreads();
    if (!s_lastg) return;

    // ---- Lean lse tail (one block per group, 128 threads). ----
    const int lane = tid & 31;
    const int wid  = tid >> 5;
    if (tid == 0) __threadfence();         // acquire side of the election
    __syncthreads();

    uint4* __restrict__ keys = (uint4*)(g_rowmax + g * NPTS);
    float acc = 0.0f;
#pragma unroll
    for (int q = 0; q < KPT; ++q) {        // 8 x LDG.128 via L2
        const int idx = tid + q * BLOCK;
        uint4 kk = __ldcg(&keys[idx]);
        keys[idx] = make_uint4(0u, 0u, 0u, 0u);   // restore sentinel
        acc += __expf(-ALPHA * unukey(kk.x));
        acc += __expf(-ALPHA * unukey(kk.y));
        acc += __expf(-ALPHA * unukey(kk.z));
        acc += __expf(-ALPHA * unukey(kk.w));
    }

#pragma unroll
    for (int o = 16; o > 0; o >>= 1)
        acc += __shfl_xor_sync(0xFFFFFFFFu, acc, o);
    if (lane == 0) sred[wid] = acc;
    __syncthreads();

    if (tid == 0) {
        float total = 0.0f;
#pragma unroll
        for (int i = 0; i < BLOCK / 32; ++i) total += sred[i];
        g_lse[g] = __logf(total) / ALPHA;
        g_done[g] = 0u;                    // reset for next replay
        __threadfence();
        unsigned int prev = atomicAdd(&g_fin, 1u);
        s_fin = (prev == NG - 1);
    }
    __syncthreads();

    if (s_fin && tid == 0) {
        float a = 0.0f, c = 0.0f;
        for (int i = 0; i < NB; ++i) {
            a += __ldcg(&g_lse[i]);
            c += __ldcg(&g_lse[NB + i]);
        }
        out[0] = 0.5f * (a / NB + c / NB);
        atomicExch(&g_fin, 0u);            // reset for next replay
    }
}

// ---------------------------------------------------------------------------
extern "C" void kernel_launch(void* const* d_in, const int* in_sizes, int n_in,
                              void* d_out, int out_size)
{
    const float* p1 = (const float*)d_in[0];
    const float* p2 = (const float*)d_in[1];
    float* out = (float*)d_out;

    dim3 grid(ROWTILES, JC, NG);   // 4 x 64 x 8 = 2048 blocks
    hausdorff_fused_kernel<<<grid, BLOCK>>>(p1, p2, out);
}

// round 17
// speedup vs baseline: 1.0666x; 1.0572x over previous
#include <cuda_runtime.h>
#include <math.h>

#define ALPHA 10.0f
#define NPTS  4096
#define NB    4
#define NG    (2 * NB)            // dir * batch groups = 8

#define BLOCK 256                 // threads per block (kernel 1)
#define RPT   8                   // rows per thread
#define JC    64                  // candidate chunks
#define CHUNK (NPTS / JC)         // 64 candidates per chunk
#define ROWTILES (NPTS / (BLOCK * RPT))  // 2

#define LSE_BLOCK 256
#define LSE_RPT   (NPTS / LSE_BLOCK)     // 16

// Row keys of t = 2*(a.b - w) - ||a||^2  (min dist = -t), monotone UNSIGNED
// encoded so that 0 == "-inf" sentinel. Zero BSS covers the first call; the
// lse kernel restores zeros after reading (self-restoring graph).
__device__ unsigned int g_rowmax[NG * NPTS];
__device__ float g_lse[NG];
__device__ unsigned int g_ctr;

// Monotone float -> unsigned key; u=0 is below every real key.
__device__ __forceinline__ unsigned int ukey(float f)
{
    int i = __float_as_int(f);
    return (i >= 0) ? ((unsigned int)i | 0x80000000u) : ~(unsigned int)i;
}
__device__ __forceinline__ float unukey(unsigned int u)
{
    int i = (u & 0x80000000u) ? (int)(u ^ 0x80000000u) : (int)~u;
    return __int_as_float(i);
}

// ---------------------------------------------------------------------------
// Packed fp32x2 helpers (sm_100a native)
// ---------------------------------------------------------------------------
__device__ __forceinline__ unsigned long long ffma2(unsigned long long a,
                                                    unsigned long long b,
                                                    unsigned long long c)
{
    unsigned long long d;
    asm("fma.rn.f32x2 %0, %1, %2, %3;" : "=l"(d) : "l"(a), "l"(b), "l"(c));
    return d;
}

__device__ __forceinline__ unsigned long long pack2(float lo, float hi)
{
    unsigned long long r;
    asm("mov.b64 %0, {%1, %2};" : "=l"(r) : "f"(lo), "f"(hi));
    return r;
}

__device__ __forceinline__ void unpack2(unsigned long long v, float& lo, float& hi)
{
    asm("mov.b64 {%0, %1}, %2;" : "=f"(lo), "=f"(hi) : "l"(v));
}

// ---------------------------------------------------------------------------
// Kernel 1: per (group, row) fold max_j of t = 2*(a.b - w) - ||a||^2 across
// candidate chunks with atomicMax on unsigned order-keys. Hot loop per
// candidate: 2 LDS.128 + 12 FFMA2 + 8 FMNMX => 8 pairs / 22 instrs.
// unroll 4 (measured best in R10; unroll 8 cost ~2us in R13).
// ---------------------------------------------------------------------------
__global__ void __launch_bounds__(BLOCK)
hausdorff_part_kernel(const float* __restrict__ p1,
                      const float* __restrict__ p2)
{
    // Each candidate: {bx,bx} {by,by} {bz,bz} {-w,-w}  (w = 0.5*||b||^2)
    __shared__ ulonglong2 sB[CHUNK * 2];   // 2 KB

    const int g   = blockIdx.z;            // 0..7
    const int dir = g >> 2;
    const int b   = g & 3;
    const int jc  = blockIdx.y;
    const int tid = threadIdx.x;

    const float* __restrict__ A  = dir ? p2 : p1;
    const float* __restrict__ Bv = dir ? p1 : p2;
    const float* __restrict__ Bb = Bv + ((size_t)b * NPTS + jc * CHUNK) * 3;

    // Fill smem: CHUNK(=64) candidates, threads 0..63.
    if (tid < CHUNK) {
        const int j = tid;
        float x = Bb[3 * j + 0];
        float y = Bb[3 * j + 1];
        float z = Bb[3 * j + 2];
        float w = -0.5f * (x * x + y * y + z * z);
        sB[2 * j + 0] = make_ulonglong2(pack2(x, x), pack2(y, y));
        sB[2 * j + 1] = make_ulonglong2(pack2(z, z), pack2(w, w));
    }
    __syncthreads();

    // Load 8 rows (strided by BLOCK for coalescing) and pack pairs.
    const int rowbase = blockIdx.x * (BLOCK * RPT);
    float ax[RPT], ay[RPT], az[RPT];
#pragma unroll
    for (int k = 0; k < RPT; ++k) {
        const int i = rowbase + tid + k * BLOCK;
        const float* __restrict__ Ai = A + ((size_t)b * NPTS + i) * 3;
        ax[k] = Ai[0];
        ay[k] = Ai[1];
        az[k] = Ai[2];
    }
    unsigned long long pax[RPT / 2], pay[RPT / 2], paz[RPT / 2];
#pragma unroll
    for (int p = 0; p < RPT / 2; ++p) {
        pax[p] = pack2(ax[2 * p], ax[2 * p + 1]);
        pay[p] = pack2(ay[2 * p], ay[2 * p + 1]);
        paz[p] = pack2(az[2 * p], az[2 * p + 1]);
    }

    float m[RPT];
#pragma unroll
    for (int k = 0; k < RPT; ++k) m[k] = -3.402823466e38f;

#pragma unroll 4
    for (int j = 0; j < CHUNK; ++j) {
        const ulonglong2 q0 = sB[2 * j + 0];   // {bx,bx} {by,by}
        const ulonglong2 q1 = sB[2 * j + 1];   // {bz,bz} {-w,-w}
#pragma unroll
        for (int p = 0; p < RPT / 2; ++p) {
            unsigned long long s = ffma2(pax[p], q0.x, q1.y);
            s = ffma2(pay[p], q0.y, s);
            s = ffma2(paz[p], q1.x, s);
            float s0, s1;
            unpack2(s, s0, s1);
            m[2 * p + 0] = fmaxf(m[2 * p + 0], s0);
            m[2 * p + 1] = fmaxf(m[2 * p + 1], s1);
        }
    }

    // t = 2*m - sq;  min dist = -t.  Max is order-independent => determinist.
#pragma unroll
    for (int k = 0; k < RPT; ++k) {
        const int row = rowbase + tid + k * BLOCK;
        const float sq = fmaf(ax[k], ax[k], fmaf(ay[k], ay[k], az[k] * az[k]));
        const float t  = fmaf(2.0f, m[k], -sq);
        atomicMax(&g_rowmax[g * NPTS + row], ukey(t));
    }
}

// ---------------------------------------------------------------------------
// Kernel 2 (fused lse + final): reads ONLY the 16KB/group key array (uint4,
// coalesced, L2-hot), restores the zero sentinel for the next replay, and
// reduces with shuffles (2 barriers total). Last block writes the scalar and
// resets the completion counter. (Measured 6.7us in R13.)
// ---------------------------------------------------------------------------
__global__ void __launch_bounds__(LSE_BLOCK)
hausdorff_lse_kernel(float* __restrict__ out)
{
    __shared__ float sred[LSE_BLOCK / 32];   // 8 warp partials
    __shared__ bool s_last;

    const int g    = blockIdx.x;
    const int tid  = threadIdx.x;
    const int lane = tid & 31;
    const int wid  = tid >> 5;

    uint4* __restrict__ keys = (uint4*)(g_rowmax + g * NPTS);

    float v[LSE_RPT];
#pragma unroll
    for (int q = 0; q < LSE_RPT / 4; ++q) {          // 4 x LDG.128, coalesced
        const int idx = tid + q * LSE_BLOCK;
        uint4 kk = keys[idx];
        v[4 * q + 0] = -ALPHA * unukey(kk.x);
        v[4 * q + 1] = -ALPHA * unukey(kk.y);
        v[4 * q + 2] = -ALPHA * unukey(kk.z);
        v[4 * q + 3] = -ALPHA * unukey(kk.w);
        keys[idx] = make_uint4(0u, 0u, 0u, 0u);      // restore sentinel
    }

    // -- max: warp shuffle, then 8-way --
    float M = v[0];
#pragma unroll
    for (int r = 1; r < LSE_RPT; ++r) M = fmaxf(M, v[r]);
#pragma unroll
    for (int o = 16; o > 0; o >>= 1)
        M = fmaxf(M, __shfl_xor_sync(0xFFFFFFFFu, M, o));
    if (lane == 0) sred[wid] = M;
    __syncthreads();
    {
        float t = sred[lane & 7];                    // 8 valid entries
#pragma unroll
        for (int o = 4; o > 0; o >>= 1)
            t = fmaxf(t, __shfl_xor_sync(0xFFFFFFFFu, t, o));
        M = t;                                       // every thread: group max
    }

    // -- sum exp (MUFU-based __expf) --
    float acc = 0.0f;
#pragma unroll
    for (int r = 0; r < LSE_RPT; ++r) acc += __expf(v[r] - M);
#pragma unroll
    for (int o = 16; o > 0; o >>= 1)
        acc += __shfl_xor_sync(0xFFFFFFFFu, acc, o);
    __syncthreads();                                 // sred reuse guard
    if (lane == 0) sred[wid] = acc;
    __syncthreads();

    if (tid == 0) {
        float total = 0.0f;
#pragma unroll
        for (int i = 0; i < LSE_BLOCK / 32; ++i) total += sred[i];
        g_lse[g] = (M + __logf(total)) / ALPHA;
        __threadfence();
        unsigned int prev = atomicAdd(&g_ctr, 1u);
        s_last = (prev == NG - 1);
    }
    __syncthreads();

    if (s_last && tid == 0) {
        float a = 0.0f, c = 0.0f;
        for (int i = 0; i < NB; ++i) {
            a += g_lse[i];
            c += g_lse[NB + i];
        }
        out[0] = 0.5f * (a / NB + c / NB);
        atomicExch(&g_ctr, 0u);                      // reset for next replay
    }
}

// ---------------------------------------------------------------------------
extern "C" void kernel_launch(void* const* d_in, const int* in_sizes, int n_in,
                              void* d_out, int out_size)
{
    const float* p1 = (const float*)d_in[0];
    const float* p2 = (const float*)d_in[1];
    float* out = (float*)d_out;

    dim3 grid(ROWTILES, JC, NG);   // 2 x 64 x 8 = 1024 blocks of 256 threads
    hausdorff_part_kernel<<<grid, BLOCK>>>(p1, p2);
    hausdorff_lse_kernel<<<NG, LSE_BLOCK>>>(out);
}